// round 7
// baseline (speedup 1.0000x reference)
#include <cuda_runtime.h>
#include <math.h>

#define HID 4096
#define LEN 2048
#define VOC 4096
#define CTX_SLICES 32   // 64 encoder rows per slice

// ---------------- scratch (device globals, no allocation) ----------------
__device__ __align__(16) float g_alog[LEN];                   // attention logits
__device__ __align__(16) float g_attn[LEN];                   // attention weights
__device__ __align__(16) float g_ctx_part[CTX_SLICES * HID];  // ctx partials (512 KB)
__device__ __align__(16) float g_ctx[HID];                    // context vector
__device__ __align__(16) float g_x[HID];                      // LSTM input
__device__ __align__(16) float g_h[HID];                      // h_new
__device__ __align__(16) float g_logits[VOC];                 // output logits

// ---------------- helpers ----------------
__device__ __forceinline__ float wred_sum(float v) {
    #pragma unroll
    for (int o = 16; o; o >>= 1) v += __shfl_xor_sync(0xffffffffu, v, o);
    return v;
}
__device__ __forceinline__ float wred_max(float v) {
    #pragma unroll
    for (int o = 16; o; o >>= 1) v = fmaxf(v, __shfl_xor_sync(0xffffffffu, v, o));
    return v;
}
__device__ __forceinline__ float block_sum(float v) {
    __shared__ float sm[33];
    int lane = threadIdx.x & 31, warp = threadIdx.x >> 5;
    v = wred_sum(v);
    if (lane == 0) sm[warp] = v;
    __syncthreads();
    int nw = (blockDim.x + 31) >> 5;
    float r = (threadIdx.x < nw) ? sm[threadIdx.x] : 0.f;
    if (warp == 0) { r = wred_sum(r); if (lane == 0) sm[32] = r; }
    __syncthreads();
    r = sm[32];
    __syncthreads();
    return r;
}
__device__ __forceinline__ float block_max(float v) {
    __shared__ float sm[33];
    int lane = threadIdx.x & 31, warp = threadIdx.x >> 5;
    v = wred_max(v);
    if (lane == 0) sm[warp] = v;
    __syncthreads();
    int nw = (blockDim.x + 31) >> 5;
    float r = (threadIdx.x < nw) ? sm[threadIdx.x] : -INFINITY;
    if (warp == 0) { r = wred_max(r); if (lane == 0) sm[32] = r; }
    __syncthreads();
    r = sm[32];
    __syncthreads();
    return r;
}

__device__ __forceinline__ float dot4(float4 w, float4 x, float acc) {
    return fmaf(w.x, x.x, fmaf(w.y, x.y, fmaf(w.z, x.z, fmaf(w.w, x.w, acc))));
}
__device__ __forceinline__ void acc4(float4& a, float4 u) {
    a.x += u.x; a.y += u.y; a.z += u.z; a.w += u.w;
}

// ---------------- kernels ----------------

// Block-cooperative GEMV: input vector(s) staged in SMEM once per block,
// then warp-per-row streams weights (__ldcs, no reuse) against SMEM.
// out[row] = ACT( W1[row]·v1 + (C2? W2[row]·v2 :0) + b1[row] + (b2? b2[row] :0) )
// If idx1 != nullptr, v1 is a 2D table and row idx1[0] is used (embedding fusion).
template<int C1, int C2, int ACT>
__global__ void k_gemv_sm(const float* __restrict__ W1, int ld1,
                          const float* __restrict__ v1, const int* __restrict__ idx1,
                          const float* __restrict__ W2, int ld2, const float* __restrict__ v2,
                          const float* __restrict__ b1, const float* __restrict__ b2,
                          float* __restrict__ out)
{
    __shared__ __align__(16) float sv[C1 + (C2 > 0 ? C2 : 0)];
    float4* s4 = reinterpret_cast<float4*>(sv);

    const float* vv1 = idx1 ? (v1 + (size_t)idx1[0] * C1) : v1;
    for (int i = threadIdx.x; i < C1 / 4; i += blockDim.x)
        s4[i] = __ldg(reinterpret_cast<const float4*>(vv1) + i);
    if constexpr (C2 > 0) {
        for (int i = threadIdx.x; i < C2 / 4; i += blockDim.x)
            s4[C1 / 4 + i] = __ldg(reinterpret_cast<const float4*>(v2) + i);
    }
    __syncthreads();

    const int lane = threadIdx.x & 31;
    const int row  = blockIdx.x * (blockDim.x >> 5) + (threadIdx.x >> 5);

    const float4* w1 = reinterpret_cast<const float4*>(W1 + (size_t)row * ld1);
    float acc0 = 0.f, acc1 = 0.f;
    #pragma unroll 4
    for (int k0 = 0; k0 < C1 / 4; k0 += 64) {
        int k = k0 + lane;
        acc0 = dot4(__ldcs(w1 + k),      s4[k],      acc0);
        acc1 = dot4(__ldcs(w1 + k + 32), s4[k + 32], acc1);
    }
    if constexpr (C2 > 0) {
        const float4* w2 = reinterpret_cast<const float4*>(W2 + (size_t)row * ld2);
        #pragma unroll 4
        for (int k0 = 0; k0 < C2 / 4; k0 += 64) {
            int k = k0 + lane;
            acc0 = dot4(__ldcs(w2 + k),      s4[C1 / 4 + k],      acc0);
            acc1 = dot4(__ldcs(w2 + k + 32), s4[C1 / 4 + k + 32], acc1);
        }
    }
    float acc = wred_sum(acc0 + acc1);
    if (lane == 0) {
        acc += b1[row];
        if (b2) acc += b2[row];
        if (ACT == 1) acc = fmaxf(acc, 0.f);
        out[row] = acc;
    }
}

// softmax over 2048 attention logits; writes g_attn and d_out[12288:14336)
__global__ void k_softmax_attn(float* __restrict__ out_attn) {
    const int t = threadIdx.x;           // 256 threads, 8 elems each
    float v[8];
    float m = -INFINITY;
    #pragma unroll
    for (int i = 0; i < 8; i++) {
        v[i] = g_alog[t + 256 * i];
        m = fmaxf(m, v[i]);
    }
    m = block_max(m);
    float s = 0.f;
    #pragma unroll
    for (int i = 0; i < 8; i++) {
        v[i] = expf(v[i] - m);
        s += v[i];
    }
    s = block_sum(s);
    float inv = 1.f / s;
    #pragma unroll
    for (int i = 0; i < 8; i++) {
        float w = v[i] * inv;
        g_attn[t + 256 * i]   = w;
        out_attn[t + 256 * i] = w;
    }
}

// ctx partial: grid(8, 32), block 128. Each block: 512 cols (128 float4) × 64 rows.
__global__ void k_ctx_partial(const float* __restrict__ enc) {
    const int col4 = blockIdx.x * 128 + threadIdx.x;    // 0..1023
    const int l0   = blockIdx.y * 64;
    const float4* e4 = reinterpret_cast<const float4*>(enc);
    float4 acc = make_float4(0.f, 0.f, 0.f, 0.f);
    #pragma unroll 8
    for (int i = 0; i < 64; ++i) {
        int l = l0 + i;
        float w = g_attn[l];
        float4 u = __ldcs(e4 + (size_t)l * (HID / 4) + col4);
        acc.x = fmaf(w, u.x, acc.x);
        acc.y = fmaf(w, u.y, acc.y);
        acc.z = fmaf(w, u.z, acc.z);
        acc.w = fmaf(w, u.w, acc.w);
    }
    reinterpret_cast<float4*>(g_ctx_part)[blockIdx.y * (HID / 4) + col4] = acc;
}

// ctx reduce: 128 blocks × 256 threads. Block handles 8 col4; thread layout
// tid = slice*8 + colIdx (coalesced 128B runs per slice). Fixed-order combine.
__global__ void k_ctx_reduce() {
    const int colIdx = threadIdx.x & 7;          // 0..7
    const int slice  = threadIdx.x >> 3;         // 0..31
    const int col4   = blockIdx.x * 8 + colIdx;  // 0..1023
    __shared__ float4 sm[32][8];
    const float4* p = reinterpret_cast<const float4*>(g_ctx_part);
    sm[slice][colIdx] = p[(size_t)slice * (HID / 4) + col4];
    __syncthreads();
    if (threadIdx.x < 8) {
        float4 r = sm[0][threadIdx.x];
        #pragma unroll
        for (int s = 1; s < CTX_SLICES; s++) acc4(r, sm[s][threadIdx.x]);
        reinterpret_cast<float4*>(g_ctx)[blockIdx.x * 8 + threadIdx.x] = r;
    }
}

// fused gates GEMV + LSTM pointwise, with x and h staged in SMEM.
// Warp per output index j: 4 gate rows over W_ih·x + W_hh·h + biases, then cell update.
__global__ void k_gates_lstm(const float* __restrict__ W_ih,
                             const float* __restrict__ W_hh,
                             const float* __restrict__ b_ih,
                             const float* __restrict__ b_hh,
                             const float* __restrict__ h,
                             const float* __restrict__ c_in,
                             float* __restrict__ out)
{
    __shared__ __align__(16) float sv[2 * HID];
    float4* s4 = reinterpret_cast<float4*>(sv);
    for (int i = threadIdx.x; i < HID / 4; i += blockDim.x)
        s4[i] = __ldg(reinterpret_cast<const float4*>(g_x) + i);
    for (int i = threadIdx.x; i < HID / 4; i += blockDim.x)
        s4[HID / 4 + i] = __ldg(reinterpret_cast<const float4*>(h) + i);
    __syncthreads();

    const int lane = threadIdx.x & 31;
    const int j = blockIdx.x * (blockDim.x >> 5) + (threadIdx.x >> 5);  // 0..4095

    float gate[4];
    #pragma unroll
    for (int gi = 0; gi < 4; gi++) {
        const int row = gi * HID + j;
        const float4* wi = reinterpret_cast<const float4*>(W_ih + (size_t)row * HID);
        const float4* wh = reinterpret_cast<const float4*>(W_hh + (size_t)row * HID);
        float a0 = 0.f, a1 = 0.f;
        #pragma unroll 4
        for (int k0 = 0; k0 < HID / 4; k0 += 64) {
            int k = k0 + lane;
            a0 = dot4(__ldcs(wi + k),      s4[k],      a0);
            a1 = dot4(__ldcs(wi + k + 32), s4[k + 32], a1);
        }
        #pragma unroll 4
        for (int k0 = 0; k0 < HID / 4; k0 += 64) {
            int k = k0 + lane;
            a0 = dot4(__ldcs(wh + k),      s4[HID / 4 + k],      a0);
            a1 = dot4(__ldcs(wh + k + 32), s4[HID / 4 + k + 32], a1);
        }
        float a = wred_sum(a0 + a1);
        gate[gi] = a + b_ih[row] + b_hh[row];
    }
    if (lane == 0) {
        float si = 1.f / (1.f + expf(-gate[0]));
        float sf = 1.f / (1.f + expf(-gate[1]));
        float so = 1.f / (1.f + expf(-gate[3]));
        float cn = sf * c_in[j] + si * tanhf(gate[2]);
        float hn = so * tanhf(cn);
        g_h[j] = hn;
        out[HID + j]     = hn;
        out[2 * HID + j] = cn;
    }
}

// log-softmax over 4096 logits -> d_out[0:4096)
__global__ void k_logsoftmax(float* __restrict__ out) {
    const int t = threadIdx.x;           // 1024 threads, 4 elems each
    float v[4];
    float m = -INFINITY;
    #pragma unroll
    for (int i = 0; i < 4; i++) {
        v[i] = g_logits[t + 1024 * i];
        m = fmaxf(m, v[i]);
    }
    m = block_max(m);
    float s = 0.f;
    #pragma unroll
    for (int i = 0; i < 4; i++) s += expf(v[i] - m);
    s = block_sum(s);
    float lse = m + logf(s);
    #pragma unroll
    for (int i = 0; i < 4; i++) out[t + 1024 * i] = v[i] - lse;
}

// ---------------- launch ----------------
extern "C" void kernel_launch(void* const* d_in, const int* in_sizes, int n_in,
                              void* d_out, int out_size)
{
    const int*   token  = (const int*)  d_in[0];
    const float* h      = (const float*)d_in[1];
    const float* c      = (const float*)d_in[2];
    const float* enc    = (const float*)d_in[3];
    const float* emb    = (const float*)d_in[4];
    const float* W_attn = (const float*)d_in[5];
    const float* b_attn = (const float*)d_in[6];
    const float* W_comb = (const float*)d_in[7];
    const float* b_comb = (const float*)d_in[8];
    const float* W_ih   = (const float*)d_in[9];
    const float* W_hh   = (const float*)d_in[10];
    const float* b_ih   = (const float*)d_in[11];
    const float* b_hh   = (const float*)d_in[12];
    const float* W_out  = (const float*)d_in[13];
    const float* b_out  = (const float*)d_in[14];
    float* out = (float*)d_out;

    // resolve scratch symbol addresses once (host-side query, capture-safe)
    static float *p_alog = nullptr, *p_x, *p_logits, *p_ctx, *p_h;
    if (!p_alog) {
        cudaGetSymbolAddress((void**)&p_alog,   g_alog);
        cudaGetSymbolAddress((void**)&p_x,      g_x);
        cudaGetSymbolAddress((void**)&p_logits, g_logits);
        cudaGetSymbolAddress((void**)&p_ctx,    g_ctx);
        cudaGetSymbolAddress((void**)&p_h,      g_h);
    }

    // 1) attention logits: [emb[token]; h] @ W_attn.T + b_attn  (2048 rows x 8192 cols)
    k_gemv_sm<4096, 4096, 0><<<LEN / 8, 256>>>(
        W_attn,         8192, emb, token,
        W_attn + 4096,  8192, h,
        b_attn, nullptr, p_alog);

    // 2) softmax -> g_attn and d_out[12288:]
    k_softmax_attn<<<1, 256>>>(out + 3 * HID);

    // 3) ctx = attn_w @ encoder_outputs (deterministic two-stage)
    k_ctx_partial<<<dim3(8, CTX_SLICES), 128>>>(enc);
    k_ctx_reduce<<<128, 256>>>();

    // 4) x = relu([emb[token]; ctx] @ W_comb.T + b_comb)  (4096 rows x 8192 cols)
    k_gemv_sm<4096, 4096, 1><<<HID / 8, 256>>>(
        W_comb,        8192, emb, token,
        W_comb + 4096, 8192, p_ctx,
        b_comb, nullptr, p_x);

    // 5) fused gates GEMV + LSTM -> h_new, c_new
    k_gates_lstm<<<HID / 8, 256>>>(W_ih, W_hh, b_ih, b_hh, h, c, out);

    // 6) logits = h_new @ W_out.T + b_out  (4096 rows x 4096 cols)
    k_gemv_sm<4096, 0, 0><<<VOC / 8, 256>>>(
        W_out, 4096, p_h, nullptr,
        nullptr, 0, nullptr,
        b_out, nullptr, p_logits);

    // 7) log-softmax -> d_out[0:4096)
    k_logsoftmax<<<1, 1024>>>(out);
}

// round 8
// speedup vs baseline: 1.1500x; 1.1500x over previous
#include <cuda_runtime.h>
#include <math.h>

#define HID 4096
#define LEN 2048
#define VOC 4096
#define CTX_SLICES 64   // 32 encoder rows per slice

// ---------------- scratch (device globals, no allocation) ----------------
__device__ __align__(16) float g_alog[LEN];                   // attention logits
__device__ __align__(16) float g_ctx_part[CTX_SLICES * HID];  // ctx partials (1 MB)
__device__ __align__(16) float g_ctx[HID];                    // context vector
__device__ __align__(16) float g_x[HID];                      // LSTM input
__device__ __align__(16) float g_ghh[4 * HID];                // W_hh·h + b_hh
__device__ __align__(16) float g_gates[4 * HID];              // full gates
__device__ __align__(16) float g_h[HID];                      // h_new
__device__ __align__(16) float g_logits[VOC];                 // output logits

// ---------------- helpers ----------------
__device__ __forceinline__ float wred_sum(float v) {
    #pragma unroll
    for (int o = 16; o; o >>= 1) v += __shfl_xor_sync(0xffffffffu, v, o);
    return v;
}
__device__ __forceinline__ float wred_max(float v) {
    #pragma unroll
    for (int o = 16; o; o >>= 1) v = fmaxf(v, __shfl_xor_sync(0xffffffffu, v, o));
    return v;
}
__device__ __forceinline__ float block_sum(float v) {
    __shared__ float sm[33];
    int lane = threadIdx.x & 31, warp = threadIdx.x >> 5;
    v = wred_sum(v);
    if (lane == 0) sm[warp] = v;
    __syncthreads();
    int nw = (blockDim.x + 31) >> 5;
    float r = (threadIdx.x < nw) ? sm[threadIdx.x] : 0.f;
    if (warp == 0) { r = wred_sum(r); if (lane == 0) sm[32] = r; }
    __syncthreads();
    r = sm[32];
    __syncthreads();
    return r;
}
__device__ __forceinline__ float block_max(float v) {
    __shared__ float sm[33];
    int lane = threadIdx.x & 31, warp = threadIdx.x >> 5;
    v = wred_max(v);
    if (lane == 0) sm[warp] = v;
    __syncthreads();
    int nw = (blockDim.x + 31) >> 5;
    float r = (threadIdx.x < nw) ? sm[threadIdx.x] : -INFINITY;
    if (warp == 0) { r = wred_max(r); if (lane == 0) sm[32] = r; }
    __syncthreads();
    r = sm[32];
    __syncthreads();
    return r;
}

__device__ __forceinline__ float dot4(float4 w, float4 x, float acc) {
    return fmaf(w.x, x.x, fmaf(w.y, x.y, fmaf(w.z, x.z, fmaf(w.w, x.w, acc))));
}
__device__ __forceinline__ void acc4(float4& a, float4 u) {
    a.x += u.x; a.y += u.y; a.z += u.z; a.w += u.w;
}

// ---------------- kernels ----------------

// R4-proven warp-per-row GEMV. Weights streamed (__ldcs); vectors via __ldg (L1-resident).
// out[row] = ACT( W1[row]·v1 + (C2? W2[row]·v2 :0) + b1[row] + (b2? b2[row] :0) )
// If idx1 != nullptr, v1 is a 2D table and row idx1[0] is used (embedding fusion).
template<int C1, int C2, int ACT>
__global__ void k_gemv2(const float* __restrict__ W1, int ld1,
                        const float* __restrict__ v1, const int* __restrict__ idx1,
                        const float* __restrict__ W2, int ld2, const float* __restrict__ v2,
                        const float* __restrict__ b1, const float* __restrict__ b2,
                        float* __restrict__ out)
{
    const int lane = threadIdx.x & 31;
    const int row  = blockIdx.x * (blockDim.x >> 5) + (threadIdx.x >> 5);

    const float* vv1 = idx1 ? (v1 + (size_t)idx1[0] * C1) : v1;
    const float4* w1 = reinterpret_cast<const float4*>(W1 + (size_t)row * ld1);
    const float4* a1 = reinterpret_cast<const float4*>(vv1);

    float acc0 = 0.f, acc1 = 0.f;
    #pragma unroll 4
    for (int k0 = 0; k0 < C1 / 4; k0 += 64) {
        int k = k0 + lane;
        acc0 = dot4(__ldcs(w1 + k),      __ldg(a1 + k),      acc0);
        acc1 = dot4(__ldcs(w1 + k + 32), __ldg(a1 + k + 32), acc1);
    }
    if constexpr (C2 > 0) {
        const float4* w2 = reinterpret_cast<const float4*>(W2 + (size_t)row * ld2);
        const float4* a2 = reinterpret_cast<const float4*>(v2);
        #pragma unroll 4
        for (int k0 = 0; k0 < C2 / 4; k0 += 64) {
            int k = k0 + lane;
            acc0 = dot4(__ldcs(w2 + k),      __ldg(a2 + k),      acc0);
            acc1 = dot4(__ldcs(w2 + k + 32), __ldg(a2 + k + 32), acc1);
        }
    }
    float acc = wred_sum(acc0 + acc1);
    if (lane == 0) {
        acc += b1[row];
        if (b2) acc += b2[row];
        if (ACT == 1) acc = fmaxf(acc, 0.f);
        out[row] = acc;
    }
}

// fused softmax + ctx partial. grid(4, 64), block 256.
// Every block recomputes the softmax (deterministic, identical in all blocks)
// from g_alog into SMEM, then streams its 1024-col x 32-row slice of enc.
// Block (0,0) additionally writes the attention weights to d_out.
__global__ void k_ctx_softmax_partial(const float* __restrict__ enc,
                                      float* __restrict__ out_attn)
{
    __shared__ float sexp[LEN];
    const int t = threadIdx.x;           // 256 threads, 8 logits each

    float v[8];
    float m = -INFINITY;
    #pragma unroll
    for (int i = 0; i < 8; i++) {
        v[i] = g_alog[t + 256 * i];
        m = fmaxf(m, v[i]);
    }
    m = block_max(m);
    float s = 0.f;
    #pragma unroll
    for (int i = 0; i < 8; i++) {
        v[i] = expf(v[i] - m);
        s += v[i];
        sexp[t + 256 * i] = v[i];
    }
    s = block_sum(s);                    // includes trailing __syncthreads
    const float inv = 1.f / s;

    if (blockIdx.x == 0 && blockIdx.y == 0) {
        #pragma unroll
        for (int i = 0; i < 8; i++)
            out_attn[t + 256 * i] = sexp[t + 256 * i] * inv;
    }

    const int col4 = blockIdx.x * 256 + t;  // 0..1023
    const int l0   = blockIdx.y * 32;
    const float4* e4 = reinterpret_cast<const float4*>(enc);
    float4 acc = make_float4(0.f, 0.f, 0.f, 0.f);
    #pragma unroll 8
    for (int i = 0; i < 32; ++i) {
        int l = l0 + i;
        float w = sexp[l] * inv;
        float4 u = __ldcs(e4 + (size_t)l * (HID / 4) + col4);
        acc.x = fmaf(w, u.x, acc.x);
        acc.y = fmaf(w, u.y, acc.y);
        acc.z = fmaf(w, u.z, acc.z);
        acc.w = fmaf(w, u.w, acc.w);
    }
    reinterpret_cast<float4*>(g_ctx_part)[blockIdx.y * (HID / 4) + col4] = acc;
}

// ctx reduce: 128 blocks x 256 threads. Block owns 8 col4 columns.
// tid = sgrp*8 + colIdx; sgrp handles slices {sgrp, sgrp+32}; fixed-order combine.
__global__ void k_ctx_reduce() {
    const int colIdx = threadIdx.x & 7;          // 0..7
    const int sgrp   = threadIdx.x >> 3;         // 0..31
    const int col4   = blockIdx.x * 8 + colIdx;  // 0..1023
    __shared__ float4 sm[32][8];
    const float4* p = reinterpret_cast<const float4*>(g_ctx_part);
    float4 a = p[(size_t)sgrp * (HID / 4) + col4];
    acc4(a, p[(size_t)(sgrp + 32) * (HID / 4) + col4]);
    sm[sgrp][colIdx] = a;
    __syncthreads();
    if (threadIdx.x < 8) {
        float4 r = sm[0][threadIdx.x];
        #pragma unroll
        for (int s = 1; s < 32; s++) acc4(r, sm[s][threadIdx.x]);
        reinterpret_cast<float4*>(g_ctx)[blockIdx.x * 8 + threadIdx.x] = r;
    }
}

// LSTM pointwise -> h_new, c_new; writes d_out[4096:8192)=h_new, d_out[8192:12288)=c_new
__global__ void k_lstm(const float* __restrict__ c_in, float* __restrict__ out) {
    const int j = blockIdx.x * blockDim.x + threadIdx.x;  // 0..4095
    float gi = g_gates[j];
    float gf = g_gates[HID + j];
    float gg = g_gates[2 * HID + j];
    float go = g_gates[3 * HID + j];
    float si = 1.f / (1.f + expf(-gi));
    float sf = 1.f / (1.f + expf(-gf));
    float so = 1.f / (1.f + expf(-go));
    float cn = sf * c_in[j] + si * tanhf(gg);
    float hn = so * tanhf(cn);
    g_h[j] = hn;
    out[HID + j]     = hn;
    out[2 * HID + j] = cn;
}

// log-softmax over 4096 logits -> d_out[0:4096)
__global__ void k_logsoftmax(float* __restrict__ out) {
    const int t = threadIdx.x;           // 1024 threads, 4 elems each
    float v[4];
    float m = -INFINITY;
    #pragma unroll
    for (int i = 0; i < 4; i++) {
        v[i] = g_logits[t + 1024 * i];
        m = fmaxf(m, v[i]);
    }
    m = block_max(m);
    float s = 0.f;
    #pragma unroll
    for (int i = 0; i < 4; i++) s += expf(v[i] - m);
    s = block_sum(s);
    float lse = m + logf(s);
    #pragma unroll
    for (int i = 0; i < 4; i++) out[t + 1024 * i] = v[i] - lse;
}

// ---------------- launch ----------------
extern "C" void kernel_launch(void* const* d_in, const int* in_sizes, int n_in,
                              void* d_out, int out_size)
{
    const int*   token  = (const int*)  d_in[0];
    const float* h      = (const float*)d_in[1];
    const float* c      = (const float*)d_in[2];
    const float* enc    = (const float*)d_in[3];
    const float* emb    = (const float*)d_in[4];
    const float* W_attn = (const float*)d_in[5];
    const float* b_attn = (const float*)d_in[6];
    const float* W_comb = (const float*)d_in[7];
    const float* b_comb = (const float*)d_in[8];
    const float* W_ih   = (const float*)d_in[9];
    const float* W_hh   = (const float*)d_in[10];
    const float* b_ih   = (const float*)d_in[11];
    const float* b_hh   = (const float*)d_in[12];
    const float* W_out  = (const float*)d_in[13];
    const float* b_out  = (const float*)d_in[14];
    float* out = (float*)d_out;

    // one-time host-side setup (first call = correctness run, not captured)
    static bool init = false;
    static cudaStream_t s2;
    static cudaEvent_t evF, evJ;
    static float *p_alog, *p_x, *p_ghh, *p_gates, *p_logits, *p_ctx, *p_h;
    if (!init) {
        cudaStreamCreateWithFlags(&s2, cudaStreamNonBlocking);
        cudaEventCreateWithFlags(&evF, cudaEventDisableTiming);
        cudaEventCreateWithFlags(&evJ, cudaEventDisableTiming);
        cudaGetSymbolAddress((void**)&p_alog,   g_alog);
        cudaGetSymbolAddress((void**)&p_x,      g_x);
        cudaGetSymbolAddress((void**)&p_ghh,    g_ghh);
        cudaGetSymbolAddress((void**)&p_gates,  g_gates);
        cudaGetSymbolAddress((void**)&p_logits, g_logits);
        cudaGetSymbolAddress((void**)&p_ctx,    g_ctx);
        cudaGetSymbolAddress((void**)&p_h,      g_h);
        init = true;
    }

    // --- fork: side stream computes ghh = W_hh·h + b_hh (256 MB, depends only on h)
    cudaEventRecord(evF, 0);
    cudaStreamWaitEvent(s2, evF, 0);
    k_gemv2<4096, 0, 0><<<(4 * HID) / 8, 256, 0, s2>>>(
        W_hh, 4096, h, nullptr,
        nullptr, 0, nullptr,
        b_hh, nullptr, p_ghh);
    cudaEventRecord(evJ, s2);

    // --- main chain ---
    // 1) attention logits: [emb[token]; h] @ W_attn.T + b_attn  (2048 rows x 8192 cols)
    k_gemv2<4096, 4096, 0><<<LEN / 8, 256>>>(
        W_attn,         8192, emb, token,
        W_attn + 4096,  8192, h,
        b_attn, nullptr, p_alog);

    // 2) fused softmax + ctx partial (writes attn weights to d_out[12288:])
    k_ctx_softmax_partial<<<dim3(4, CTX_SLICES), 256>>>(enc, out + 3 * HID);
    k_ctx_reduce<<<128, 256>>>();

    // 3) x = relu([emb[token]; ctx] @ W_comb.T + b_comb)  (4096 rows x 8192 cols)
    k_gemv2<4096, 4096, 1><<<HID / 8, 256>>>(
        W_comb,        8192, emb, token,
        W_comb + 4096, 8192, p_ctx,
        b_comb, nullptr, p_x);

    // --- join: gates = W_ih·x + b_ih + ghh
    cudaStreamWaitEvent(0, evJ, 0);
    k_gemv2<4096, 0, 0><<<(4 * HID) / 8, 256>>>(
        W_ih, 4096, p_x, nullptr,
        nullptr, 0, nullptr,
        b_ih, p_ghh, p_gates);

    // 4) LSTM pointwise -> h_new, c_new (also written to d_out)
    k_lstm<<<HID / 256, 256>>>(c, out);

    // 5) logits = h_new @ W_out.T + b_out  (4096 rows x 4096 cols)
    k_gemv2<4096, 0, 0><<<VOC / 8, 256>>>(
        W_out, 4096, p_h, nullptr,
        nullptr, 0, nullptr,
        b_out, nullptr, p_logits);

    // 6) log-softmax -> d_out[0:4096)
    k_logsoftmax<<<1, 1024>>>(out);
}